// round 10
// baseline (speedup 1.0000x reference)
#include <cuda_runtime.h>
#include <cuda_bf16.h>
#include <math.h>
#include <stdint.h>

#define NN 25000
#define EE 400000

// ---------------- device scratch ----------------
__device__ int   g_deg[NN];
__device__ int   g_rowptr[NN + 1];
__device__ int   g_cursor[NN];
__device__ int   g_ssrc[EE];
__device__ float g_uvx[NN * 768];
__device__ float g_pc[NN * 768];
__device__ float g_lin[NN * 256];
__device__ float g_alpha[NN];
__device__ float g_beta[NN];
__device__ float g_bnsum[256];
__device__ float g_bnsq[256];
__device__ __nv_bfloat16 g_xh[NN * 128],   g_xl[NN * 128];
__device__ __nv_bfloat16 g_hh[NN * 256],   g_hl[NN * 256];
__device__ __nv_bfloat16 g_aggh[NN * 1024], g_aggl[NN * 1024];
__device__ __nv_bfloat16 g_posth[NN * 256], g_postl[NN * 256];

// bf16 weight pool (hi/lo), element offsets
#define OFF_UVX 0
#define OFF_CAT 98304
#define OFF_LIN 294912
#define POOL    360448
__device__ __nv_bfloat16 g_ph[POOL];
__device__ __nv_bfloat16 g_pl[POOL];
__device__ float g_bias[1024];   // [0,768): uvx bias; [768,1024): lin bias

__device__ __forceinline__ uint32_t s2u(const void* p) {
    return (uint32_t)__cvta_generic_to_shared(p);
}
__device__ __forceinline__ void bsplit(float v, __nv_bfloat16* oh, __nv_bfloat16* ol) {
    __nv_bfloat16 h = __float2bfloat16(v);
    *oh = h;
    *ol = __float2bfloat16(v - __bfloat162float(h));
}

// ---------------- CSR build ----------------
__global__ void k_zero_int(int* p, int n) {
    int i = blockIdx.x * blockDim.x + threadIdx.x;
    if (i < n) p[i] = 0;
}
__global__ void k_zero_f(float* p, int n) {
    int i = blockIdx.x * blockDim.x + threadIdx.x;
    if (i < n) p[i] = 0.f;
}
__global__ void k_hist(const int* __restrict__ eidx) {
    int e = blockIdx.x * blockDim.x + threadIdx.x;
    if (e < EE) atomicAdd(&g_deg[eidx[EE + e]], 1);
}
__global__ void k_scan() {
    __shared__ int part[1024];
    const int CH = (NN + 1023) / 1024;
    int t = threadIdx.x;
    int base = t * CH;
    int s = 0;
    for (int i = 0; i < CH; i++) {
        int idx = base + i;
        if (idx < NN) s += g_deg[idx];
    }
    part[t] = s;
    __syncthreads();
    for (int off = 1; off < 1024; off <<= 1) {
        int v = 0;
        if (t >= off) v = part[t - off];
        __syncthreads();
        part[t] += v;
        __syncthreads();
    }
    int run = (t == 0) ? 0 : part[t - 1];
    for (int i = 0; i < CH; i++) {
        int idx = base + i;
        if (idx < NN) {
            g_rowptr[idx] = run;
            g_cursor[idx] = run;
            run += g_deg[idx];
        }
    }
    if (t == 1023) g_rowptr[NN] = EE;
}
__global__ void k_scatter(const int* __restrict__ eidx) {
    int e = blockIdx.x * blockDim.x + threadIdx.x;
    if (e < EE) {
        int tgt = eidx[EE + e];
        int pos = atomicAdd(&g_cursor[tgt], 1);
        g_ssrc[pos] = eidx[e];
    }
}

// ---------------- activation split ----------------
__global__ void k_split(const float* __restrict__ in, __nv_bfloat16* __restrict__ oh,
                        __nv_bfloat16* __restrict__ ol, int n) {
    int i = blockIdx.x * blockDim.x + threadIdx.x;
    if (i < n) bsplit(in[i], oh + i, ol + i);
}

// ---------------- weight prep ----------------
__device__ __forceinline__ void put_w(float w, int out_idx) {
    bsplit(w, g_ph + out_idx, g_pl + out_idx);
}
// Merged B layout: UVX rows [top(TF) | bot(TF) | x(TF)], K=Fin.
// CAT rows [t, blk, f] K=TF.  LIN rows linN, K=linK.
__global__ void k_prep(const float* __restrict__ preW, const float* __restrict__ preB,
                       const float* __restrict__ postW, const float* __restrict__ postB,
                       const float* __restrict__ linW, const float* __restrict__ linB,
                       int Fin, int F, int linN, int linK) {
    int TF = 4 * F;
    int KW = Fin + 12 * F;
    int sUVX = 3 * TF * Fin;
    int sCAT = 3 * TF * TF;
    int sLIN = linN * linK;
    int sB = 3 * TF + linN;
    int total = sUVX + sCAT + sLIN + sB;
    for (int i = blockIdx.x * blockDim.x + threadIdx.x; i < total; i += gridDim.x * blockDim.x) {
        if (i < sUVX) {
            int n = i / Fin, k = i % Fin;
            float w;
            if (n < TF) {
                int t = n / F, f = n % F;
                w = preW[(t * 2 * Fin + k) * F + f];
            } else if (n < 2 * TF) {
                int m = n - TF;
                int t = m / F, f = m % F;
                w = preW[(t * 2 * Fin + Fin + k) * F + f];
            } else {
                int m = n - 2 * TF;
                int t = m / F, f = m % F;
                w = postW[(t * KW + k) * F + f];
            }
            put_w(w, OFF_UVX + n * Fin + k);
        } else if (i < sUVX + sCAT) {
            int j = i - sUVX;
            int r = j / TF, k = j % TF;
            int t = r / (3 * F);
            int n2 = r % (3 * F);
            int blk = n2 / F, f = n2 % F;
            put_w(postW[(t * KW + Fin + blk * TF + k) * F + f], OFF_CAT + r * TF + k);
        } else if (i < sUVX + sCAT + sLIN) {
            int j = i - sUVX - sCAT;
            int n = j / linK, k = j % linK;
            put_w(linW[k * linN + n], OFF_LIN + n * linK + k);
        } else {
            int j = i - sUVX - sCAT - sLIN;
            if (j < 3 * TF) {
                float b = (j < TF) ? preB[j] : (j < 2 * TF ? 0.f : postB[j - 2 * TF]);
                g_bias[j] = b;
            } else {
                g_bias[768 + (j - 3 * TF)] = linB[j - 3 * TF];
            }
        }
    }
}

// ---------------- mma helpers ----------------
#define LDMX4(r, addr)                                                              \
    asm volatile("ldmatrix.sync.aligned.m8n8.x4.shared.b16 {%0,%1,%2,%3}, [%4];"    \
                 : "=r"((r)[0]), "=r"((r)[1]), "=r"((r)[2]), "=r"((r)[3])           \
                 : "r"(addr))
__device__ __forceinline__ void mma16816(float* c, const uint32_t* a, const uint32_t* b) {
    asm volatile(
        "mma.sync.aligned.m16n8k16.row.col.f32.bf16.bf16.f32 "
        "{%0,%1,%2,%3}, {%4,%5,%6,%7}, {%8,%9}, {%0,%1,%2,%3};"
        : "+f"(c[0]), "+f"(c[1]), "+f"(c[2]), "+f"(c[3])
        : "r"(a[0]), "r"(a[1]), "r"(a[2]), "r"(a[3]), "r"(b[0]), "r"(b[1]));
}
#define CPA(d, s, pb) \
    asm volatile("cp.async.ca.shared.global [%0], [%1], 16, %2;\n" ::"r"(d), "l"(s), "r"(pb))
#define CP_COMMIT() asm volatile("cp.async.commit_group;\n" ::: "memory")
#define CP_WAIT1() asm volatile("cp.async.wait_group 1;\n" ::: "memory")
#define CP_WAIT0() asm volatile("cp.async.wait_group 0;\n" ::: "memory")

// ---------------- bf16x3 GEMM, CTA 64x64, 128 thr, 4 warps, 2-stage cp.async ----------------
// C[row, coff + z*cz + col] = sum_k A[z*az + row*lda + k] * B[z][col, k] (+bias[col])
// smem/stage: Ah 5120 | Al 5120 | Bh 5120 | Bl 5120 = 20480; 2 stages = 40960.
__global__ __launch_bounds__(128, 4) void k_gemm2(
    const __nv_bfloat16* __restrict__ Ah, const __nv_bfloat16* __restrict__ Al,
    int lda, int az,
    const __nv_bfloat16* __restrict__ Bh, const __nv_bfloat16* __restrict__ Bl,
    int bz, int Nz,
    const float* __restrict__ bias, float* __restrict__ C, int ldc, int coff, int cz,
    int M, int K) {
    extern __shared__ char smem[];
    const int STG = 20480;
    uint32_t sbase = s2u(smem);
    int tid = threadIdx.x;
    int w = tid >> 5, lane = tid & 31;
    int wm = w & 1, wn = w >> 1;
    int bm = blockIdx.x * 64, bn = blockIdx.y * 64;
    int z = blockIdx.z;

    const __nv_bfloat16* A0h = Ah + (size_t)z * az;
    const __nv_bfloat16* A0l = Al + (size_t)z * az;
    const __nv_bfloat16* B0h = Bh + (size_t)z * bz;
    const __nv_bfloat16* B0l = Bl + (size_t)z * bz;

    int lrow = tid >> 1;          // 0..63
    int lq0 = (tid & 1) * 2;      // segment pair {0,1} or {2,3}

    auto issue = [&](int i) {
        int s = i & 1;
        uint32_t sb = sbase + s * STG;
        int k0 = i * 32;
        {
            int rg = bm + lrow;
            int pb = (rg < M) ? 16 : 0;
            int rc = (rg < M) ? rg : (M - 1);
            const __nv_bfloat16* sh = A0h + (size_t)rc * lda + k0 + lq0 * 8;
            const __nv_bfloat16* sl = A0l + (size_t)rc * lda + k0 + lq0 * 8;
            uint32_t d = sb + lrow * 80 + lq0 * 16;
            CPA(d, sh, pb);
            CPA(d + 16, sh + 8, pb);
            CPA(d + 5120, sl, pb);
            CPA(d + 5120 + 16, sl + 8, pb);
        }
        {
            int rg = bn + lrow;
            int pb = (rg < Nz) ? 16 : 0;
            int rc = (rg < Nz) ? rg : (Nz - 1);
            const __nv_bfloat16* sh = B0h + (size_t)rc * K + k0 + lq0 * 8;
            const __nv_bfloat16* sl = B0l + (size_t)rc * K + k0 + lq0 * 8;
            uint32_t d = sb + 10240 + lrow * 80 + lq0 * 16;
            CPA(d, sh, pb);
            CPA(d + 16, sh + 8, pb);
            CPA(d + 5120, sl, pb);
            CPA(d + 5120 + 16, sl + 8, pb);
        }
        CP_COMMIT();
    };

    float acc[2][4][4] = {};
    int nch = K / 32;
    issue(0);
    for (int i = 0; i < nch; i++) {
        if (i + 1 < nch) {
            issue(i + 1);
            CP_WAIT1();
        } else {
            CP_WAIT0();
        }
        __syncthreads();
        uint32_t sb = sbase + (i & 1) * STG;
#pragma unroll
        for (int ks = 0; ks < 2; ks++) {
            uint32_t ah[2][4], al[2][4], bh[4][2], bl[4][2];
#pragma unroll
            for (int mi = 0; mi < 2; mi++) {
                int r = wm * 32 + mi * 16 + (lane & 15);
                int kk = ks * 16 + ((lane >> 4) << 3);
                uint32_t ad = sb + r * 80 + kk * 2;
                LDMX4(ah[mi], ad);
                LDMX4(al[mi], ad + 5120);
            }
#pragma unroll
            for (int np = 0; np < 2; np++) {
                int rr = wn * 32 + np * 16 + (lane & 7) + ((lane & 16) ? 8 : 0);
                int kk = ks * 16 + ((lane & 8) ? 8 : 0);
                uint32_t bd = sb + 10240 + rr * 80 + kk * 2;
                uint32_t t[4];
                LDMX4(t, bd);
                bh[np * 2][0] = t[0]; bh[np * 2][1] = t[1];
                bh[np * 2 + 1][0] = t[2]; bh[np * 2 + 1][1] = t[3];
                LDMX4(t, bd + 5120);
                bl[np * 2][0] = t[0]; bl[np * 2][1] = t[1];
                bl[np * 2 + 1][0] = t[2]; bl[np * 2 + 1][1] = t[3];
            }
#pragma unroll
            for (int mi = 0; mi < 2; mi++)
#pragma unroll
                for (int ni = 0; ni < 4; ni++) {
                    mma16816(acc[mi][ni], ah[mi], bh[ni]);
                    mma16816(acc[mi][ni], ah[mi], bl[ni]);
                    mma16816(acc[mi][ni], al[mi], bh[ni]);
                }
        }
        __syncthreads();
    }

    // epilogue
#pragma unroll
    for (int mi = 0; mi < 2; mi++) {
#pragma unroll
        for (int ni = 0; ni < 4; ni++) {
            int col = bn + wn * 32 + ni * 8 + 2 * (lane & 3);
            if (col >= Nz) continue;
            float bv0 = bias ? bias[col] : 0.f;
            float bv1 = bias ? bias[col + 1] : 0.f;
            int r0 = bm + wm * 32 + mi * 16 + (lane >> 2);
            size_t cb = (size_t)coff + (size_t)z * cz + col;
            if (r0 < M) {
                float2 o = make_float2(acc[mi][ni][0] + bv0, acc[mi][ni][1] + bv1);
                *(float2*)(C + (size_t)r0 * ldc + cb) = o;
            }
            if (r0 + 8 < M) {
                float2 o = make_float2(acc[mi][ni][2] + bv0, acc[mi][ni][3] + bv1);
                *(float2*)(C + (size_t)(r0 + 8) * ldc + cb) = o;
            }
        }
    }
}

// ---------------- segment reduce (writes agg directly as bf16 hi/lo) ----------------
template <int C, int F>
__global__ void k_segreduce(const float* __restrict__ uvx, int ld, int voff,
                            __nv_bfloat16* __restrict__ aggh, __nv_bfloat16* __restrict__ aggl,
                            float* __restrict__ alpha, float* __restrict__ beta,
                            const float* __restrict__ avg_log) {
    int n = blockIdx.x;
    int j = threadIdx.x;
    int beg = g_rowptr[n], end = g_rowptr[n + 1];
    float s = 0.f, s2 = 0.f, mn = 3.4e38f, mx = -3.4e38f;
    for (int e = beg; e < end; e++) {
        int sidx = g_ssrc[e];
        float val = uvx[(size_t)sidx * ld + voff + j];
        s += val;
        s2 += val * val;
        mn = fminf(mn, val);
        mx = fmaxf(mx, val);
    }
    int deg = end - beg;
    float uu = uvx[(size_t)n * ld + j];
    float degf = (float)deg;
    float degc = fmaxf(degf, 1.f);
    float mean = (deg > 0) ? (uu + s / degf) : 0.f;
    float s2f = degf * uu * uu + 2.f * uu * s + s2;
    float var = fmaxf(s2f / degc - mean * mean, 0.f);
    float sd = sqrtf(var + 1e-5f);
    float mnv = (deg > 0) ? (uu + mn) : 0.f;
    float mxv = (deg > 0) ? (uu + mx) : 0.f;
    int t = j / F, f = j % F;
    size_t base = (size_t)n * (4 * C) + t * (4 * F);
    bsplit(mean, aggh + base + f, aggl + base + f);
    bsplit(mnv, aggh + base + F + f, aggl + base + F + f);
    bsplit(mxv, aggh + base + 2 * F + f, aggl + base + 2 * F + f);
    bsplit(sd, aggh + base + 3 * F + f, aggl + base + 3 * F + f);
    if (j == 0) {
        float dl = logf(degc + 1.f);
        alpha[n] = dl / avg_log[0];
        beta[n] = avg_log[0] / dl;
    }
}

// ---------------- combine: post = px + p1 + a*p2 + b*p3 -> bf16 hi/lo ----------------
__global__ void k_combine(const float* __restrict__ uvx, int ld, int pxoff,
                          const float* __restrict__ pc, int ldpc,
                          const float* __restrict__ alpha, const float* __restrict__ beta,
                          __nv_bfloat16* __restrict__ oh, __nv_bfloat16* __restrict__ ol,
                          int C, int F) {
    int idx = blockIdx.x * blockDim.x + threadIdx.x;
    if (idx < NN * C) {
        int n = idx / C, c = idx % C;
        int t = c / F, f = c % F;
        const float* p = pc + (size_t)n * ldpc + t * 3 * F;
        float v = uvx[(size_t)n * ld + pxoff + c] + p[f] + alpha[n] * p[F + f] +
                  beta[n] * p[2 * F + f];
        bsplit(v, oh + idx, ol + idx);
    }
}

// ---------------- batchnorm ----------------
__global__ void k_bnstats(const float* __restrict__ Y, float* __restrict__ sum,
                          float* __restrict__ sq, int M, int C) {
    int j = threadIdx.x;
    if (j >= C) return;
    float s = 0.f, q = 0.f;
    for (int r = blockIdx.x; r < M; r += gridDim.x) {
        float v = Y[(size_t)r * C + j];
        if (!isfinite(v)) v = 0.f;
        s += v;
        q += v * v;
    }
    atomicAdd(&sum[j], s);
    atomicAdd(&sq[j], q);
}
// relu(bn) -> bf16 hi/lo
__global__ void k_bnapply_split(const float* __restrict__ Y, const float* __restrict__ sum,
                                const float* __restrict__ sq, const float* __restrict__ g,
                                const float* __restrict__ b, __nv_bfloat16* __restrict__ oh,
                                __nv_bfloat16* __restrict__ ol, int M, int C) {
    int idx = blockIdx.x * blockDim.x + threadIdx.x;
    if (idx < M * C) {
        int j = idx % C;
        float m = sum[j] / (float)M;
        float var = sq[j] / (float)M - m * m;
        float inv = rsqrtf(var + 1e-5f);
        float y = Y[idx];
        if (!isfinite(y)) y = 0.f;
        float o = fmaxf(0.f, g[j] * (y - m) * inv + b[j]);
        bsplit(o, oh + idx, ol + idx);
    }
}
// relu(bn) -> fp32 (final output)
__global__ void k_bnapply_out(const float* __restrict__ Y, const float* __restrict__ sum,
                              const float* __restrict__ sq, const float* __restrict__ g,
                              const float* __restrict__ b, float* __restrict__ OUT, int M,
                              int C) {
    int idx = blockIdx.x * blockDim.x + threadIdx.x;
    if (idx < M * C) {
        int j = idx % C;
        float m = sum[j] / (float)M;
        float var = sq[j] / (float)M - m * m;
        float inv = rsqrtf(var + 1e-5f);
        float y = Y[idx];
        if (!isfinite(y)) y = 0.f;
        OUT[idx] = fmaxf(0.f, g[j] * (y - m) * inv + b[j]);
    }
}

// ---------------- launch ----------------
extern "C" void kernel_launch(void* const* d_in, const int* in_sizes, int n_in,
                              void* d_out, int out_size) {
    const float* x       = (const float*)d_in[0];
    const int*   eidx    = (const int*)d_in[1];
    const float* avg_log = (const float*)d_in[2];
    const float* pre1W   = (const float*)d_in[3];
    const float* pre1b   = (const float*)d_in[4];
    const float* post1W  = (const float*)d_in[5];
    const float* post1b  = (const float*)d_in[6];
    const float* lin1W   = (const float*)d_in[7];
    const float* lin1b   = (const float*)d_in[8];
    const float* bn1g    = (const float*)d_in[9];
    const float* bn1b    = (const float*)d_in[10];
    const float* pre2W   = (const float*)d_in[11];
    const float* pre2b   = (const float*)d_in[12];
    const float* post2W  = (const float*)d_in[13];
    const float* post2b  = (const float*)d_in[14];
    const float* lin2W   = (const float*)d_in[15];
    const float* lin2b   = (const float*)d_in[16];
    const float* bn2g    = (const float*)d_in[17];
    const float* bn2b    = (const float*)d_in[18];

    int* deg;
    float *uvx, *pc, *lin, *alpha, *beta, *bnsum, *bnsq, *bias;
    __nv_bfloat16 *xh, *xl, *hh, *hl, *aggh, *aggl, *posth, *postl, *ph, *pl;
    cudaGetSymbolAddress((void**)&deg, g_deg);
    cudaGetSymbolAddress((void**)&uvx, g_uvx);
    cudaGetSymbolAddress((void**)&pc, g_pc);
    cudaGetSymbolAddress((void**)&lin, g_lin);
    cudaGetSymbolAddress((void**)&alpha, g_alpha);
    cudaGetSymbolAddress((void**)&beta, g_beta);
    cudaGetSymbolAddress((void**)&bnsum, g_bnsum);
    cudaGetSymbolAddress((void**)&bnsq, g_bnsq);
    cudaGetSymbolAddress((void**)&bias, g_bias);
    cudaGetSymbolAddress((void**)&xh, g_xh);
    cudaGetSymbolAddress((void**)&xl, g_xl);
    cudaGetSymbolAddress((void**)&hh, g_hh);
    cudaGetSymbolAddress((void**)&hl, g_hl);
    cudaGetSymbolAddress((void**)&aggh, g_aggh);
    cudaGetSymbolAddress((void**)&aggl, g_aggl);
    cudaGetSymbolAddress((void**)&posth, g_posth);
    cudaGetSymbolAddress((void**)&postl, g_postl);
    cudaGetSymbolAddress((void**)&ph, g_ph);
    cudaGetSymbolAddress((void**)&pl, g_pl);

    const int SMEM = 40960;  // 2 stages x 20480
    cudaFuncSetAttribute(k_gemm2, cudaFuncAttributeMaxDynamicSharedMemorySize, SMEM);

    const int mt = (NN + 63) / 64;  // 391

    // =================== layer 1 (Fin=128, F=64, TF=256) ===================
    k_prep<<<512, 256>>>(pre1W, pre1b, post1W, post1b, lin1W, lin1b, 128, 64, 256, 256);
    k_split<<<(NN * 128 + 255) / 256, 256>>>(x, xh, xl, NN * 128);
    k_zero_int<<<(NN + 255) / 256, 256>>>(deg, NN);
    k_hist<<<(EE + 255) / 256, 256>>>(eidx);
    k_scan<<<1, 1024>>>();
    // merged u|v|px : [NN,768] = x @ B_uvx
    k_gemm2<<<dim3(mt, 12, 1), 128, SMEM>>>(xh, xl, 128, 0, ph + OFF_UVX, pl + OFF_UVX,
                                            0, 768, bias, uvx, 768, 0, 0, NN, 128);
    k_scatter<<<(EE + 255) / 256, 256>>>(eidx);

    k_segreduce<256, 64><<<NN, 256>>>(uvx, 768, 256, aggh, aggl, alpha, beta, avg_log);
    // cat: per-tower agg @ [W1|W2|W3]
    k_gemm2<<<dim3(mt, 3, 4), 128, SMEM>>>(aggh, aggl, 1024, 256, ph + OFF_CAT, pl + OFF_CAT,
                                           192 * 256, 192, nullptr, pc, 768, 0, 192, NN, 256);
    k_combine<<<(NN * 256 + 255) / 256, 256>>>(uvx, 768, 512, pc, 768, alpha, beta,
                                               posth, postl, 256, 64);
    k_gemm2<<<dim3(mt, 4, 1), 128, SMEM>>>(posth, postl, 256, 0, ph + OFF_LIN, pl + OFF_LIN,
                                           0, 256, bias + 768, lin, 256, 0, 0, NN, 256);
    k_zero_f<<<1, 256>>>(bnsum, 256);
    k_zero_f<<<1, 256>>>(bnsq, 256);
    k_bnstats<<<512, 256>>>(lin, bnsum, bnsq, NN, 256);
    k_bnapply_split<<<(NN * 256 + 255) / 256, 256>>>(lin, bnsum, bnsq, bn1g, bn1b, hh, hl,
                                                     NN, 256);

    // =================== layer 2 (Fin=256, F=32, TF=128) ===================
    k_prep<<<512, 256>>>(pre2W, pre2b, post2W, post2b, lin2W, lin2b, 256, 32, 128, 128);
    k_gemm2<<<dim3(mt, 6, 1), 128, SMEM>>>(hh, hl, 256, 0, ph + OFF_UVX, pl + OFF_UVX,
                                           0, 384, bias, uvx, 384, 0, 0, NN, 256);
    k_segreduce<128, 32><<<NN, 128>>>(uvx, 384, 128, aggh, aggl, alpha, beta, avg_log);
    k_gemm2<<<dim3(mt, 2, 4), 128, SMEM>>>(aggh, aggl, 512, 128, ph + OFF_CAT, pl + OFF_CAT,
                                           96 * 128, 96, nullptr, pc, 384, 0, 96, NN, 128);
    k_combine<<<(NN * 128 + 255) / 256, 256>>>(uvx, 384, 256, pc, 384, alpha, beta,
                                               posth, postl, 128, 32);
    k_gemm2<<<dim3(mt, 2, 1), 128, SMEM>>>(posth, postl, 128, 0, ph + OFF_LIN, pl + OFF_LIN,
                                           0, 128, bias + 768, lin, 128, 0, 0, NN, 128);
    k_zero_f<<<1, 256>>>(bnsum, 256);
    k_zero_f<<<1, 256>>>(bnsq, 256);
    k_bnstats<<<512, 128>>>(lin, bnsum, bnsq, NN, 128);
    k_bnapply_out<<<(NN * 128 + 255) / 256, 256>>>(lin, bnsum, bnsq, bn2g, bn2b,
                                                   (float*)d_out, NN, 128);
}

// round 11
// speedup vs baseline: 1.1124x; 1.1124x over previous
#include <cuda_runtime.h>
#include <cuda_bf16.h>
#include <math.h>
#include <stdint.h>

#define NN 25000
#define EE 400000

// ---------------- device scratch ----------------
__device__ int   g_deg[NN];
__device__ int   g_rowptr[NN + 1];
__device__ int   g_cursor[NN];
__device__ int   g_ssrc[EE];
__device__ float g_uvx[NN * 768];
__device__ float g_pc[NN * 768];
__device__ float g_lin[NN * 256];
__device__ float g_alpha[NN];
__device__ float g_beta[NN];
__device__ float g_bnsum[256];
__device__ float g_bnsq[256];
__device__ __nv_bfloat16 g_xh[NN * 128],   g_xl[NN * 128];
__device__ __nv_bfloat16 g_hh[NN * 256],   g_hl[NN * 256];
__device__ __nv_bfloat16 g_aggh[NN * 1024], g_aggl[NN * 1024];
__device__ __nv_bfloat16 g_posth[NN * 256], g_postl[NN * 256];

// bf16 weight pool (hi/lo), element offsets
#define OFF_UVX 0
#define OFF_CAT 98304
#define OFF_LIN 294912
#define POOL    360448
__device__ __nv_bfloat16 g_ph[POOL];
__device__ __nv_bfloat16 g_pl[POOL];
__device__ float g_bias[1024];   // [0,768): uvx bias; [768,1024): lin bias

__device__ __forceinline__ uint32_t s2u(const void* p) {
    return (uint32_t)__cvta_generic_to_shared(p);
}
__device__ __forceinline__ void bsplit(float v, __nv_bfloat16* oh, __nv_bfloat16* ol) {
    __nv_bfloat16 h = __float2bfloat16(v);
    *oh = h;
    *ol = __float2bfloat16(v - __bfloat162float(h));
}

// ---------------- CSR build ----------------
__global__ void k_zero_int(int* p, int n) {
    int i = blockIdx.x * blockDim.x + threadIdx.x;
    if (i < n) p[i] = 0;
}
__global__ void k_zero_f(float* p, int n) {
    int i = blockIdx.x * blockDim.x + threadIdx.x;
    if (i < n) p[i] = 0.f;
}
__global__ void k_hist(const int* __restrict__ eidx) {
    int e = blockIdx.x * blockDim.x + threadIdx.x;
    if (e < EE) atomicAdd(&g_deg[eidx[EE + e]], 1);
}
__global__ void k_scan() {
    __shared__ int part[1024];
    const int CH = (NN + 1023) / 1024;
    int t = threadIdx.x;
    int base = t * CH;
    int s = 0;
    for (int i = 0; i < CH; i++) {
        int idx = base + i;
        if (idx < NN) s += g_deg[idx];
    }
    part[t] = s;
    __syncthreads();
    for (int off = 1; off < 1024; off <<= 1) {
        int v = 0;
        if (t >= off) v = part[t - off];
        __syncthreads();
        part[t] += v;
        __syncthreads();
    }
    int run = (t == 0) ? 0 : part[t - 1];
    for (int i = 0; i < CH; i++) {
        int idx = base + i;
        if (idx < NN) {
            g_rowptr[idx] = run;
            g_cursor[idx] = run;
            run += g_deg[idx];
        }
    }
    if (t == 1023) g_rowptr[NN] = EE;
}
__global__ void k_scatter(const int* __restrict__ eidx) {
    int e = blockIdx.x * blockDim.x + threadIdx.x;
    if (e < EE) {
        int tgt = eidx[EE + e];
        int pos = atomicAdd(&g_cursor[tgt], 1);
        g_ssrc[pos] = eidx[e];
    }
}

// ---------------- activation split ----------------
__global__ void k_split(const float* __restrict__ in, __nv_bfloat16* __restrict__ oh,
                        __nv_bfloat16* __restrict__ ol, int n) {
    int i = blockIdx.x * blockDim.x + threadIdx.x;
    if (i < n) bsplit(in[i], oh + i, ol + i);
}

// ---------------- weight prep ----------------
__device__ __forceinline__ void put_w(float w, int out_idx) {
    bsplit(w, g_ph + out_idx, g_pl + out_idx);
}
// Merged B layout: UVX rows [top(TF) | bot(TF) | x(TF)], K=Fin.
// CAT rows [t, blk, f] K=TF.  LIN rows linN, K=linK.
__global__ void k_prep(const float* __restrict__ preW, const float* __restrict__ preB,
                       const float* __restrict__ postW, const float* __restrict__ postB,
                       const float* __restrict__ linW, const float* __restrict__ linB,
                       int Fin, int F, int linN, int linK) {
    int TF = 4 * F;
    int KW = Fin + 12 * F;
    int sUVX = 3 * TF * Fin;
    int sCAT = 3 * TF * TF;
    int sLIN = linN * linK;
    int sB = 3 * TF + linN;
    int total = sUVX + sCAT + sLIN + sB;
    for (int i = blockIdx.x * blockDim.x + threadIdx.x; i < total; i += gridDim.x * blockDim.x) {
        if (i < sUVX) {
            int n = i / Fin, k = i % Fin;
            float w;
            if (n < TF) {
                int t = n / F, f = n % F;
                w = preW[(t * 2 * Fin + k) * F + f];
            } else if (n < 2 * TF) {
                int m = n - TF;
                int t = m / F, f = m % F;
                w = preW[(t * 2 * Fin + Fin + k) * F + f];
            } else {
                int m = n - 2 * TF;
                int t = m / F, f = m % F;
                w = postW[(t * KW + k) * F + f];
            }
            put_w(w, OFF_UVX + n * Fin + k);
        } else if (i < sUVX + sCAT) {
            int j = i - sUVX;
            int r = j / TF, k = j % TF;
            int t = r / (3 * F);
            int n2 = r % (3 * F);
            int blk = n2 / F, f = n2 % F;
            put_w(postW[(t * KW + Fin + blk * TF + k) * F + f], OFF_CAT + r * TF + k);
        } else if (i < sUVX + sCAT + sLIN) {
            int j = i - sUVX - sCAT;
            int n = j / linK, k = j % linK;
            put_w(linW[k * linN + n], OFF_LIN + n * linK + k);
        } else {
            int j = i - sUVX - sCAT - sLIN;
            if (j < 3 * TF) {
                float b = (j < TF) ? preB[j] : (j < 2 * TF ? 0.f : postB[j - 2 * TF]);
                g_bias[j] = b;
            } else {
                g_bias[768 + (j - 3 * TF)] = linB[j - 3 * TF];
            }
        }
    }
}

// ---------------- mma helpers ----------------
#define LDMX4(r, addr)                                                              \
    asm volatile("ldmatrix.sync.aligned.m8n8.x4.shared.b16 {%0,%1,%2,%3}, [%4];"    \
                 : "=r"((r)[0]), "=r"((r)[1]), "=r"((r)[2]), "=r"((r)[3])           \
                 : "r"(addr))
__device__ __forceinline__ void mma16816(float* c, const uint32_t* a, const uint32_t* b) {
    asm volatile(
        "mma.sync.aligned.m16n8k16.row.col.f32.bf16.bf16.f32 "
        "{%0,%1,%2,%3}, {%4,%5,%6,%7}, {%8,%9}, {%0,%1,%2,%3};"
        : "+f"(c[0]), "+f"(c[1]), "+f"(c[2]), "+f"(c[3])
        : "r"(a[0]), "r"(a[1]), "r"(a[2]), "r"(a[3]), "r"(b[0]), "r"(b[1]));
}
#define CPA(d, s, pb) \
    asm volatile("cp.async.ca.shared.global [%0], [%1], 16, %2;\n" ::"r"(d), "l"(s), "r"(pb))
#define CP_COMMIT() asm volatile("cp.async.commit_group;\n" ::: "memory")
#define CP_WAIT1() asm volatile("cp.async.wait_group 1;\n" ::: "memory")
#define CP_WAIT0() asm volatile("cp.async.wait_group 0;\n" ::: "memory")

// ---------------- bf16x3 GEMM, round-7 shell + term-interleaved MMA order ----------------
// C[row, coff + z*cz + col] = sum_k A[z*az + row*lda + k] * B[z][col, k] (+bias[col])
// Tile 128Mx64N, 256 thr, KC=32, 2-stage cp.async, dual sync (measured-best shell).
__global__ __launch_bounds__(256, 2) void k_gemm2(
    const __nv_bfloat16* __restrict__ Ah, const __nv_bfloat16* __restrict__ Al,
    int lda, int az,
    const __nv_bfloat16* __restrict__ Bh, const __nv_bfloat16* __restrict__ Bl,
    int bz, int Nz,
    const float* __restrict__ bias, float* __restrict__ C, int ldc, int coff, int cz,
    int M, int K) {
    extern __shared__ char smem[];
    const int STG = 30720;  // per stage: Ah 10240 | Al 10240 | Bh 5120 | Bl 5120
    uint32_t sbase = s2u(smem);
    int tid = threadIdx.x;
    int w = tid >> 5, lane = tid & 31;
    int wm = w & 3, wn = w >> 2;
    int bm = blockIdx.x * 128, bn = blockIdx.y * 64;
    int z = blockIdx.z;

    const __nv_bfloat16* A0h = Ah + (size_t)z * az;
    const __nv_bfloat16* A0l = Al + (size_t)z * az;
    const __nv_bfloat16* B0h = Bh + (size_t)z * bz;
    const __nv_bfloat16* B0l = Bl + (size_t)z * bz;

    int arow = tid >> 2, aq = tid & 3;

    auto issue = [&](int i) {
        int s = i & 1;
        uint32_t sb = sbase + s * STG;
        int k0 = i * 32;
#pragma unroll
        for (int r = 0; r < 2; r++) {
            int row = arow + r * 64;
            int rg = bm + row;
            int pb = (rg < M) ? 16 : 0;
            int rc = (rg < M) ? rg : (M - 1);
            const __nv_bfloat16* sh = A0h + (size_t)rc * lda + k0 + aq * 8;
            const __nv_bfloat16* sl = A0l + (size_t)rc * lda + k0 + aq * 8;
            uint32_t d = sb + row * 80 + aq * 16;
            CPA(d, sh, pb);
            CPA(d + 10240, sl, pb);
        }
        {
            int rg = bn + arow;
            int pb = (rg < Nz) ? 16 : 0;
            int rc = (rg < Nz) ? rg : (Nz - 1);
            const __nv_bfloat16* sh = B0h + (size_t)rc * K + k0 + aq * 8;
            const __nv_bfloat16* sl = B0l + (size_t)rc * K + k0 + aq * 8;
            uint32_t d = sb + 20480 + arow * 80 + aq * 16;
            CPA(d, sh, pb);
            CPA(d + 5120, sl, pb);
        }
        CP_COMMIT();
    };

    float acc[2][4][4] = {};
    int nch = K / 32;
    issue(0);
    for (int i = 0; i < nch; i++) {
        if (i + 1 < nch) {
            issue(i + 1);
            CP_WAIT1();
        } else {
            CP_WAIT0();
        }
        __syncthreads();
        uint32_t sb = sbase + (i & 1) * STG;
#pragma unroll
        for (int ks = 0; ks < 2; ks++) {
            uint32_t ah[2][4], al[2][4], bh[4][2], bl[4][2];
#pragma unroll
            for (int mi = 0; mi < 2; mi++) {
                int r = wm * 32 + mi * 16 + (lane & 15);
                int kk = ks * 16 + ((lane >> 4) << 3);
                uint32_t ad = sb + r * 80 + kk * 2;
                LDMX4(ah[mi], ad);
                LDMX4(al[mi], ad + 10240);
            }
#pragma unroll
            for (int np = 0; np < 2; np++) {
                int rr = wn * 32 + np * 16 + (lane & 7) + ((lane & 16) ? 8 : 0);
                int kk = ks * 16 + ((lane & 8) ? 8 : 0);
                uint32_t bd = sb + 20480 + rr * 80 + kk * 2;
                uint32_t t[4];
                LDMX4(t, bd);
                bh[np * 2][0] = t[0]; bh[np * 2][1] = t[1];
                bh[np * 2 + 1][0] = t[2]; bh[np * 2 + 1][1] = t[3];
                LDMX4(t, bd + 5120);
                bl[np * 2][0] = t[0]; bl[np * 2][1] = t[1];
                bl[np * 2 + 1][0] = t[2]; bl[np * 2 + 1][1] = t[3];
            }
            // term-interleaved order: 8 independent accumulators between
            // successive uses of the same acc -> RAW latency hidden.
#pragma unroll
            for (int mi = 0; mi < 2; mi++)
#pragma unroll
                for (int ni = 0; ni < 4; ni++) mma16816(acc[mi][ni], ah[mi], bh[ni]);
#pragma unroll
            for (int mi = 0; mi < 2; mi++)
#pragma unroll
                for (int ni = 0; ni < 4; ni++) mma16816(acc[mi][ni], ah[mi], bl[ni]);
#pragma unroll
            for (int mi = 0; mi < 2; mi++)
#pragma unroll
                for (int ni = 0; ni < 4; ni++) mma16816(acc[mi][ni], al[mi], bh[ni]);
        }
        __syncthreads();
    }

    // epilogue
#pragma unroll
    for (int mi = 0; mi < 2; mi++) {
#pragma unroll
        for (int ni = 0; ni < 4; ni++) {
            int col = bn + wn * 32 + ni * 8 + 2 * (lane & 3);
            if (col >= Nz) continue;
            float bv0 = bias ? bias[col] : 0.f;
            float bv1 = bias ? bias[col + 1] : 0.f;
            int r0 = bm + wm * 32 + mi * 16 + (lane >> 2);
            size_t cb = (size_t)coff + (size_t)z * cz + col;
            if (r0 < M) {
                float2 o = make_float2(acc[mi][ni][0] + bv0, acc[mi][ni][1] + bv1);
                *(float2*)(C + (size_t)r0 * ldc + cb) = o;
            }
            if (r0 + 8 < M) {
                float2 o = make_float2(acc[mi][ni][2] + bv0, acc[mi][ni][3] + bv1);
                *(float2*)(C + (size_t)(r0 + 8) * ldc + cb) = o;
            }
        }
    }
}

// ---------------- segment reduce (writes agg directly as bf16 hi/lo) ----------------
template <int C, int F>
__global__ void k_segreduce(const float* __restrict__ uvx, int ld, int voff,
                            __nv_bfloat16* __restrict__ aggh, __nv_bfloat16* __restrict__ aggl,
                            float* __restrict__ alpha, float* __restrict__ beta,
                            const float* __restrict__ avg_log) {
    int n = blockIdx.x;
    int j = threadIdx.x;
    int beg = g_rowptr[n], end = g_rowptr[n + 1];
    float s = 0.f, s2 = 0.f, mn = 3.4e38f, mx = -3.4e38f;
    for (int e = beg; e < end; e++) {
        int sidx = g_ssrc[e];
        float val = uvx[(size_t)sidx * ld + voff + j];
        s += val;
        s2 += val * val;
        mn = fminf(mn, val);
        mx = fmaxf(mx, val);
    }
    int deg = end - beg;
    float uu = uvx[(size_t)n * ld + j];
    float degf = (float)deg;
    float degc = fmaxf(degf, 1.f);
    float mean = (deg > 0) ? (uu + s / degf) : 0.f;
    float s2f = degf * uu * uu + 2.f * uu * s + s2;
    float var = fmaxf(s2f / degc - mean * mean, 0.f);
    float sd = sqrtf(var + 1e-5f);
    float mnv = (deg > 0) ? (uu + mn) : 0.f;
    float mxv = (deg > 0) ? (uu + mx) : 0.f;
    int t = j / F, f = j % F;
    size_t base = (size_t)n * (4 * C) + t * (4 * F);
    bsplit(mean, aggh + base + f, aggl + base + f);
    bsplit(mnv, aggh + base + F + f, aggl + base + F + f);
    bsplit(mxv, aggh + base + 2 * F + f, aggl + base + 2 * F + f);
    bsplit(sd, aggh + base + 3 * F + f, aggl + base + 3 * F + f);
    if (j == 0) {
        float dl = logf(degc + 1.f);
        alpha[n] = dl / avg_log[0];
        beta[n] = avg_log[0] / dl;
    }
}

// ---------------- combine: post = px + p1 + a*p2 + b*p3 -> bf16 hi/lo ----------------
__global__ void k_combine(const float* __restrict__ uvx, int ld, int pxoff,
                          const float* __restrict__ pc, int ldpc,
                          const float* __restrict__ alpha, const float* __restrict__ beta,
                          __nv_bfloat16* __restrict__ oh, __nv_bfloat16* __restrict__ ol,
                          int C, int F) {
    int idx = blockIdx.x * blockDim.x + threadIdx.x;
    if (idx < NN * C) {
        int n = idx / C, c = idx % C;
        int t = c / F, f = c % F;
        const float* p = pc + (size_t)n * ldpc + t * 3 * F;
        float v = uvx[(size_t)n * ld + pxoff + c] + p[f] + alpha[n] * p[F + f] +
                  beta[n] * p[2 * F + f];
        bsplit(v, oh + idx, ol + idx);
    }
}

// ---------------- batchnorm ----------------
__global__ void k_bnstats(const float* __restrict__ Y, float* __restrict__ sum,
                          float* __restrict__ sq, int M, int C) {
    int j = threadIdx.x;
    if (j >= C) return;
    float s = 0.f, q = 0.f;
    for (int r = blockIdx.x; r < M; r += gridDim.x) {
        float v = Y[(size_t)r * C + j];
        if (!isfinite(v)) v = 0.f;
        s += v;
        q += v * v;
    }
    atomicAdd(&sum[j], s);
    atomicAdd(&sq[j], q);
}
// relu(bn) -> bf16 hi/lo
__global__ void k_bnapply_split(const float* __restrict__ Y, const float* __restrict__ sum,
                                const float* __restrict__ sq, const float* __restrict__ g,
                                const float* __restrict__ b, __nv_bfloat16* __restrict__ oh,
                                __nv_bfloat16* __restrict__ ol, int M, int C) {
    int idx = blockIdx.x * blockDim.x + threadIdx.x;
    if (idx < M * C) {
        int j = idx % C;
        float m = sum[j] / (float)M;
        float var = sq[j] / (float)M - m * m;
        float inv = rsqrtf(var + 1e-5f);
        float y = Y[idx];
        if (!isfinite(y)) y = 0.f;
        float o = fmaxf(0.f, g[j] * (y - m) * inv + b[j]);
        bsplit(o, oh + idx, ol + idx);
    }
}
// relu(bn) -> fp32 (final output)
__global__ void k_bnapply_out(const float* __restrict__ Y, const float* __restrict__ sum,
                              const float* __restrict__ sq, const float* __restrict__ g,
                              const float* __restrict__ b, float* __restrict__ OUT, int M,
                              int C) {
    int idx = blockIdx.x * blockDim.x + threadIdx.x;
    if (idx < M * C) {
        int j = idx % C;
        float m = sum[j] / (float)M;
        float var = sq[j] / (float)M - m * m;
        float inv = rsqrtf(var + 1e-5f);
        float y = Y[idx];
        if (!isfinite(y)) y = 0.f;
        OUT[idx] = fmaxf(0.f, g[j] * (y - m) * inv + b[j]);
    }
}

// ---------------- launch ----------------
extern "C" void kernel_launch(void* const* d_in, const int* in_sizes, int n_in,
                              void* d_out, int out_size) {
    const float* x       = (const float*)d_in[0];
    const int*   eidx    = (const int*)d_in[1];
    const float* avg_log = (const float*)d_in[2];
    const float* pre1W   = (const float*)d_in[3];
    const float* pre1b   = (const float*)d_in[4];
    const float* post1W  = (const float*)d_in[5];
    const float* post1b  = (const float*)d_in[6];
    const float* lin1W   = (const float*)d_in[7];
    const float* lin1b   = (const float*)d_in[8];
    const float* bn1g    = (const float*)d_in[9];
    const float* bn1b    = (const float*)d_in[10];
    const float* pre2W   = (const float*)d_in[11];
    const float* pre2b   = (const float*)d_in[12];
    const float* post2W  = (const float*)d_in[13];
    const float* post2b  = (const float*)d_in[14];
    const float* lin2W   = (const float*)d_in[15];
    const float* lin2b   = (const float*)d_in[16];
    const float* bn2g    = (const float*)d_in[17];
    const float* bn2b    = (const float*)d_in[18];

    int* deg;
    float *uvx, *pc, *lin, *alpha, *beta, *bnsum, *bnsq, *bias;
    __nv_bfloat16 *xh, *xl, *hh, *hl, *aggh, *aggl, *posth, *postl, *ph, *pl;
    cudaGetSymbolAddress((void**)&deg, g_deg);
    cudaGetSymbolAddress((void**)&uvx, g_uvx);
    cudaGetSymbolAddress((void**)&pc, g_pc);
    cudaGetSymbolAddress((void**)&lin, g_lin);
    cudaGetSymbolAddress((void**)&alpha, g_alpha);
    cudaGetSymbolAddress((void**)&beta, g_beta);
    cudaGetSymbolAddress((void**)&bnsum, g_bnsum);
    cudaGetSymbolAddress((void**)&bnsq, g_bnsq);
    cudaGetSymbolAddress((void**)&bias, g_bias);
    cudaGetSymbolAddress((void**)&xh, g_xh);
    cudaGetSymbolAddress((void**)&xl, g_xl);
    cudaGetSymbolAddress((void**)&hh, g_hh);
    cudaGetSymbolAddress((void**)&hl, g_hl);
    cudaGetSymbolAddress((void**)&aggh, g_aggh);
    cudaGetSymbolAddress((void**)&aggl, g_aggl);
    cudaGetSymbolAddress((void**)&posth, g_posth);
    cudaGetSymbolAddress((void**)&postl, g_postl);
    cudaGetSymbolAddress((void**)&ph, g_ph);
    cudaGetSymbolAddress((void**)&pl, g_pl);

    const int SMEM = 61440;  // 2 stages x 30720
    cudaFuncSetAttribute(k_gemm2, cudaFuncAttributeMaxDynamicSharedMemorySize, SMEM);

    const int mt = (NN + 127) / 128;  // 196

    // =================== layer 1 (Fin=128, F=64, TF=256) ===================
    // Launch order keeps the merged uvx GEMM at slot 6 (ncu -s 5 -c 1 capture).
    k_prep<<<512, 256>>>(pre1W, pre1b, post1W, post1b, lin1W, lin1b, 128, 64, 256, 256);
    k_split<<<(NN * 128 + 255) / 256, 256>>>(x, xh, xl, NN * 128);
    k_zero_int<<<(NN + 255) / 256, 256>>>(deg, NN);
    k_hist<<<(EE + 255) / 256, 256>>>(eidx);
    k_scan<<<1, 1024>>>();
    // merged u|v|px : [NN,768] = x @ B_uvx   (slot 6)
    k_gemm2<<<dim3(mt, 12, 1), 256, SMEM>>>(xh, xl, 128, 0, ph + OFF_UVX, pl + OFF_UVX,
                                            0, 768, bias, uvx, 768, 0, 0, NN, 128);
    k_scatter<<<(EE + 255) / 256, 256>>>(eidx);

    k_segreduce<256, 64><<<NN, 256>>>(uvx, 768, 256, aggh, aggl, alpha, beta, avg_log);
    // cat: per-tower agg @ [W1|W2|W3]
    k_gemm2<<<dim3(mt, 3, 4), 256, SMEM>>>(aggh, aggl, 1024, 256, ph + OFF_CAT, pl + OFF_CAT,
                                           192 * 256, 192, nullptr, pc, 768, 0, 192, NN, 256);
    k_combine<<<(NN * 256 + 255) / 256, 256>>>(uvx, 768, 512, pc, 768, alpha, beta,
                                               posth, postl, 256, 64);
    k_gemm2<<<dim3(mt, 4, 1), 256, SMEM>>>(posth, postl, 256, 0, ph + OFF_LIN, pl + OFF_LIN,
                                           0, 256, bias + 768, lin, 256, 0, 0, NN, 256);
    k_zero_f<<<1, 256>>>(bnsum, 256);
    k_zero_f<<<1, 256>>>(bnsq, 256);
    k_bnstats<<<512, 256>>>(lin, bnsum, bnsq, NN, 256);
    k_bnapply_split<<<(NN * 256 + 255) / 256, 256>>>(lin, bnsum, bnsq, bn1g, bn1b, hh, hl,
                                                     NN, 256);

    // =================== layer 2 (Fin=256, F=32, TF=128) ===================
    k_prep<<<512, 256>>>(pre2W, pre2b, post2W, post2b, lin2W, lin2b, 256, 32, 128, 128);
    k_gemm2<<<dim3(mt, 6, 1), 256, SMEM>>>(hh, hl, 256, 0, ph + OFF_UVX, pl + OFF_UVX,
                                           0, 384, bias, uvx, 384, 0, 0, NN, 256);
    k_segreduce<128, 32><<<NN, 128>>>(uvx, 384, 128, aggh, aggl, alpha, beta, avg_log);
    k_gemm2<<<dim3(mt, 2, 4), 256, SMEM>>>(aggh, aggl, 512, 128, ph + OFF_CAT, pl + OFF_CAT,
                                           96 * 128, 96, nullptr, pc, 384, 0, 96, NN, 128);
    k_combine<<<(NN * 128 + 255) / 256, 256>>>(uvx, 384, 256, pc, 384, alpha, beta,
                                               posth, postl, 128, 32);
    k_gemm2<<<dim3(mt, 2, 1), 256, SMEM>>>(posth, postl, 128, 0, ph + OFF_LIN, pl + OFF_LIN,
                                           0, 128, bias + 768, lin, 128, 0, 0, NN, 128);
    k_zero_f<<<1, 256>>>(bnsum, 256);
    k_zero_f<<<1, 256>>>(bnsq, 256);
    k_bnstats<<<512, 128>>>(lin, bnsum, bnsq, NN, 128);
    k_bnapply_out<<<(NN * 128 + 255) / 256, 256>>>(lin, bnsum, bnsq, bn2g, bn2b,
                                                   (float*)d_out, NN, 128);
}

// round 13
// speedup vs baseline: 1.1750x; 1.0563x over previous
#include <cuda_runtime.h>
#include <cuda_bf16.h>
#include <math.h>
#include <stdint.h>

#define NN 25000
#define EE 400000

// ---------------- device scratch ----------------
__device__ int   g_deg[NN];
__device__ int   g_rowptr[NN + 1];
__device__ int   g_cursor[NN];
__device__ int   g_ssrc[EE];
__device__ float g_uvx[NN * 768];
__device__ float g_pc[NN * 768];
__device__ float g_lin[NN * 256];
__device__ float g_alpha[NN];
__device__ float g_beta[NN];
__device__ float g_bnsum[256];
__device__ float g_bnsq[256];
__device__ __nv_bfloat16 g_xh[NN * 128],   g_xl[NN * 128];
__device__ __nv_bfloat16 g_hh[NN * 256],   g_hl[NN * 256];
__device__ __nv_bfloat16 g_aggh[NN * 1024], g_aggl[NN * 1024];
__device__ __nv_bfloat16 g_posth[NN * 256], g_postl[NN * 256];

// bf16 weight pool (hi/lo), element offsets
#define OFF_UVX 0
#define OFF_CAT 98304
#define OFF_LIN 294912
#define POOL    360448
__device__ __nv_bfloat16 g_ph[POOL];
__device__ __nv_bfloat16 g_pl[POOL];
__device__ float g_bias[1024];   // [0,768): uvx bias; [768,1024): lin bias

__device__ __forceinline__ uint32_t s2u(const void* p) {
    return (uint32_t)__cvta_generic_to_shared(p);
}
__device__ __forceinline__ void bsplit(float v, __nv_bfloat16* oh, __nv_bfloat16* ol) {
    __nv_bfloat16 h = __float2bfloat16(v);
    *oh = h;
    *ol = __float2bfloat16(v - __bfloat162float(h));
}
__device__ __forceinline__ uint32_t pack_hi2(float a, float b, uint32_t* lo) {
    __nv_bfloat16 ha = __float2bfloat16(a), hb = __float2bfloat16(b);
    __nv_bfloat162 l2;
    l2.x = __float2bfloat16(a - __bfloat162float(ha));
    l2.y = __float2bfloat16(b - __bfloat162float(hb));
    *lo = *(uint32_t*)&l2;
    __nv_bfloat162 h2; h2.x = ha; h2.y = hb;
    return *(uint32_t*)&h2;
}

// ---------------- CSR build ----------------
__global__ void k_zero_int(int* p, int n) {
    int i = blockIdx.x * blockDim.x + threadIdx.x;
    if (i < n) p[i] = 0;
}
__global__ void k_zero_f(float* p, int n) {
    int i = blockIdx.x * blockDim.x + threadIdx.x;
    if (i < n) p[i] = 0.f;
}
__global__ void k_hist(const int* __restrict__ eidx) {
    int e = blockIdx.x * blockDim.x + threadIdx.x;
    if (e < EE) atomicAdd(&g_deg[eidx[EE + e]], 1);
}
__global__ void k_scan() {
    __shared__ int part[1024];
    const int CH = (NN + 1023) / 1024;
    int t = threadIdx.x;
    int base = t * CH;
    int s = 0;
    for (int i = 0; i < CH; i++) {
        int idx = base + i;
        if (idx < NN) s += g_deg[idx];
    }
    part[t] = s;
    __syncthreads();
    for (int off = 1; off < 1024; off <<= 1) {
        int v = 0;
        if (t >= off) v = part[t - off];
        __syncthreads();
        part[t] += v;
        __syncthreads();
    }
    int run = (t == 0) ? 0 : part[t - 1];
    for (int i = 0; i < CH; i++) {
        int idx = base + i;
        if (idx < NN) {
            g_rowptr[idx] = run;
            g_cursor[idx] = run;
            run += g_deg[idx];
        }
    }
    if (t == 1023) g_rowptr[NN] = EE;
}
__global__ void k_scatter(const int* __restrict__ eidx) {
    int e = blockIdx.x * blockDim.x + threadIdx.x;
    if (e < EE) {
        int tgt = eidx[EE + e];
        int pos = atomicAdd(&g_cursor[tgt], 1);
        g_ssrc[pos] = eidx[e];
    }
}

// ---------------- activation split (float4 vectorized) ----------------
__global__ void k_split(const float* __restrict__ in, __nv_bfloat16* __restrict__ oh,
                        __nv_bfloat16* __restrict__ ol, int n4) {
    int i = blockIdx.x * blockDim.x + threadIdx.x;
    if (i < n4) {
        float4 v = ((const float4*)in)[i];
        uint32_t l0, l1;
        uint32_t h0 = pack_hi2(v.x, v.y, &l0);
        uint32_t h1 = pack_hi2(v.z, v.w, &l1);
        ((uint2*)oh)[i] = make_uint2(h0, h1);
        ((uint2*)ol)[i] = make_uint2(l0, l1);
    }
}

// ---------------- weight prep ----------------
__device__ __forceinline__ void put_w(float w, int out_idx) {
    bsplit(w, g_ph + out_idx, g_pl + out_idx);
}
__global__ void k_prep(const float* __restrict__ preW, const float* __restrict__ preB,
                       const float* __restrict__ postW, const float* __restrict__ postB,
                       const float* __restrict__ linW, const float* __restrict__ linB,
                       int Fin, int F, int linN, int linK) {
    int TF = 4 * F;
    int KW = Fin + 12 * F;
    int sUVX = 3 * TF * Fin;
    int sCAT = 3 * TF * TF;
    int sLIN = linN * linK;
    int sB = 3 * TF + linN;
    int total = sUVX + sCAT + sLIN + sB;
    for (int i = blockIdx.x * blockDim.x + threadIdx.x; i < total; i += gridDim.x * blockDim.x) {
        if (i < sUVX) {
            int n = i / Fin, k = i % Fin;
            float w;
            if (n < TF) {
                int t = n / F, f = n % F;
                w = preW[(t * 2 * Fin + k) * F + f];
            } else if (n < 2 * TF) {
                int m = n - TF;
                int t = m / F, f = m % F;
                w = preW[(t * 2 * Fin + Fin + k) * F + f];
            } else {
                int m = n - 2 * TF;
                int t = m / F, f = m % F;
                w = postW[(t * KW + k) * F + f];
            }
            put_w(w, OFF_UVX + n * Fin + k);
        } else if (i < sUVX + sCAT) {
            int j = i - sUVX;
            int r = j / TF, k = j % TF;
            int t = r / (3 * F);
            int n2 = r % (3 * F);
            int blk = n2 / F, f = n2 % F;
            put_w(postW[(t * KW + Fin + blk * TF + k) * F + f], OFF_CAT + r * TF + k);
        } else if (i < sUVX + sCAT + sLIN) {
            int j = i - sUVX - sCAT;
            int n = j / linK, k = j % linK;
            put_w(linW[k * linN + n], OFF_LIN + n * linK + k);
        } else {
            int j = i - sUVX - sCAT - sLIN;
            if (j < 3 * TF) {
                float b = (j < TF) ? preB[j] : (j < 2 * TF ? 0.f : postB[j - 2 * TF]);
                g_bias[j] = b;
            } else {
                g_bias[768 + (j - 3 * TF)] = linB[j - 3 * TF];
            }
        }
    }
}

// ---------------- mma helpers ----------------
#define LDMX4(r, addr)                                                              \
    asm volatile("ldmatrix.sync.aligned.m8n8.x4.shared.b16 {%0,%1,%2,%3}, [%4];"    \
                 : "=r"((r)[0]), "=r"((r)[1]), "=r"((r)[2]), "=r"((r)[3])           \
                 : "r"(addr))
__device__ __forceinline__ void mma16816(float* c, const uint32_t* a, const uint32_t* b) {
    asm volatile(
        "mma.sync.aligned.m16n8k16.row.col.f32.bf16.bf16.f32 "
        "{%0,%1,%2,%3}, {%4,%5,%6,%7}, {%8,%9}, {%0,%1,%2,%3};"
        : "+f"(c[0]), "+f"(c[1]), "+f"(c[2]), "+f"(c[3])
        : "r"(a[0]), "r"(a[1]), "r"(a[2]), "r"(a[3]), "r"(b[0]), "r"(b[1]));
}
#define CPA(d, s, pb) \
    asm volatile("cp.async.ca.shared.global [%0], [%1], 16, %2;\n" ::"r"(d), "l"(s), "r"(pb))
#define CP_COMMIT() asm volatile("cp.async.commit_group;\n" ::: "memory")
#define CP_WAIT1() asm volatile("cp.async.wait_group 1;\n" ::: "memory")
#define CP_WAIT0() asm volatile("cp.async.wait_group 0;\n" ::: "memory")

// ---------------- bf16x3 GEMM (champion shell, unchanged) ----------------
__global__ __launch_bounds__(256, 2) void k_gemm2(
    const __nv_bfloat16* __restrict__ Ah, const __nv_bfloat16* __restrict__ Al,
    int lda, int az,
    const __nv_bfloat16* __restrict__ Bh, const __nv_bfloat16* __restrict__ Bl,
    int bz, int Nz,
    const float* __restrict__ bias, float* __restrict__ C, int ldc, int coff, int cz,
    int M, int K) {
    extern __shared__ char smem[];
    const int STG = 30720;
    uint32_t sbase = s2u(smem);
    int tid = threadIdx.x;
    int w = tid >> 5, lane = tid & 31;
    int wm = w & 3, wn = w >> 2;
    int bm = blockIdx.x * 128, bn = blockIdx.y * 64;
    int z = blockIdx.z;

    const __nv_bfloat16* A0h = Ah + (size_t)z * az;
    const __nv_bfloat16* A0l = Al + (size_t)z * az;
    const __nv_bfloat16* B0h = Bh + (size_t)z * bz;
    const __nv_bfloat16* B0l = Bl + (size_t)z * bz;

    int arow = tid >> 2, aq = tid & 3;

    auto issue = [&](int i) {
        int s = i & 1;
        uint32_t sb = sbase + s * STG;
        int k0 = i * 32;
#pragma unroll
        for (int r = 0; r < 2; r++) {
            int row = arow + r * 64;
            int rg = bm + row;
            int pb = (rg < M) ? 16 : 0;
            int rc = (rg < M) ? rg : (M - 1);
            const __nv_bfloat16* sh = A0h + (size_t)rc * lda + k0 + aq * 8;
            const __nv_bfloat16* sl = A0l + (size_t)rc * lda + k0 + aq * 8;
            uint32_t d = sb + row * 80 + aq * 16;
            CPA(d, sh, pb);
            CPA(d + 10240, sl, pb);
        }
        {
            int rg = bn + arow;
            int pb = (rg < Nz) ? 16 : 0;
            int rc = (rg < Nz) ? rg : (Nz - 1);
            const __nv_bfloat16* sh = B0h + (size_t)rc * K + k0 + aq * 8;
            const __nv_bfloat16* sl = B0l + (size_t)rc * K + k0 + aq * 8;
            uint32_t d = sb + 20480 + arow * 80 + aq * 16;
            CPA(d, sh, pb);
            CPA(d + 5120, sl, pb);
        }
        CP_COMMIT();
    };

    float acc[2][4][4] = {};
    int nch = K / 32;
    issue(0);
    for (int i = 0; i < nch; i++) {
        if (i + 1 < nch) {
            issue(i + 1);
            CP_WAIT1();
        } else {
            CP_WAIT0();
        }
        __syncthreads();
        uint32_t sb = sbase + (i & 1) * STG;
#pragma unroll
        for (int ks = 0; ks < 2; ks++) {
            uint32_t ah[2][4], al[2][4], bh[4][2], bl[4][2];
#pragma unroll
            for (int mi = 0; mi < 2; mi++) {
                int r = wm * 32 + mi * 16 + (lane & 15);
                int kk = ks * 16 + ((lane >> 4) << 3);
                uint32_t ad = sb + r * 80 + kk * 2;
                LDMX4(ah[mi], ad);
                LDMX4(al[mi], ad + 10240);
            }
#pragma unroll
            for (int np = 0; np < 2; np++) {
                int rr = wn * 32 + np * 16 + (lane & 7) + ((lane & 16) ? 8 : 0);
                int kk = ks * 16 + ((lane & 8) ? 8 : 0);
                uint32_t bd = sb + 20480 + rr * 80 + kk * 2;
                uint32_t t[4];
                LDMX4(t, bd);
                bh[np * 2][0] = t[0]; bh[np * 2][1] = t[1];
                bh[np * 2 + 1][0] = t[2]; bh[np * 2 + 1][1] = t[3];
                LDMX4(t, bd + 5120);
                bl[np * 2][0] = t[0]; bl[np * 2][1] = t[1];
                bl[np * 2 + 1][0] = t[2]; bl[np * 2 + 1][1] = t[3];
            }
#pragma unroll
            for (int mi = 0; mi < 2; mi++)
#pragma unroll
                for (int ni = 0; ni < 4; ni++) mma16816(acc[mi][ni], ah[mi], bh[ni]);
#pragma unroll
            for (int mi = 0; mi < 2; mi++)
#pragma unroll
                for (int ni = 0; ni < 4; ni++) mma16816(acc[mi][ni], ah[mi], bl[ni]);
#pragma unroll
            for (int mi = 0; mi < 2; mi++)
#pragma unroll
                for (int ni = 0; ni < 4; ni++) mma16816(acc[mi][ni], al[mi], bh[ni]);
        }
        __syncthreads();
    }

#pragma unroll
    for (int mi = 0; mi < 2; mi++) {
#pragma unroll
        for (int ni = 0; ni < 4; ni++) {
            int col = bn + wn * 32 + ni * 8 + 2 * (lane & 3);
            if (col >= Nz) continue;
            float bv0 = bias ? bias[col] : 0.f;
            float bv1 = bias ? bias[col + 1] : 0.f;
            int r0 = bm + wm * 32 + mi * 16 + (lane >> 2);
            size_t cb = (size_t)coff + (size_t)z * cz + col;
            if (r0 < M) {
                float2 o = make_float2(acc[mi][ni][0] + bv0, acc[mi][ni][1] + bv1);
                *(float2*)(C + (size_t)r0 * ldc + cb) = o;
            }
            if (r0 + 8 < M) {
                float2 o = make_float2(acc[mi][ni][2] + bv0, acc[mi][ni][3] + bv1);
                *(float2*)(C + (size_t)(r0 + 8) * ldc + cb) = o;
            }
        }
    }
}

// ---------------- segment reduce (x4 edge unroll for MLP) ----------------
template <int C, int F>
__global__ void k_segreduce(const float* __restrict__ uvx, int ld, int voff,
                            __nv_bfloat16* __restrict__ aggh, __nv_bfloat16* __restrict__ aggl,
                            float* __restrict__ alpha, float* __restrict__ beta,
                            const float* __restrict__ avg_log) {
    int n = blockIdx.x;
    int j = threadIdx.x;
    int beg = g_rowptr[n], end = g_rowptr[n + 1];
    float s = 0.f, s2 = 0.f, mn = 3.4e38f, mx = -3.4e38f;
    int e = beg;
    for (; e + 4 <= end; e += 4) {
        int i0 = g_ssrc[e], i1 = g_ssrc[e + 1], i2 = g_ssrc[e + 2], i3 = g_ssrc[e + 3];
        float v0 = uvx[(size_t)i0 * ld + voff + j];
        float v1 = uvx[(size_t)i1 * ld + voff + j];
        float v2 = uvx[(size_t)i2 * ld + voff + j];
        float v3 = uvx[(size_t)i3 * ld + voff + j];
        s += (v0 + v1) + (v2 + v3);
        s2 += (v0 * v0 + v1 * v1) + (v2 * v2 + v3 * v3);
        mn = fminf(mn, fminf(fminf(v0, v1), fminf(v2, v3)));
        mx = fmaxf(mx, fmaxf(fmaxf(v0, v1), fmaxf(v2, v3)));
    }
    for (; e < end; e++) {
        int sidx = g_ssrc[e];
        float val = uvx[(size_t)sidx * ld + voff + j];
        s += val;
        s2 += val * val;
        mn = fminf(mn, val);
        mx = fmaxf(mx, val);
    }
    int deg = end - beg;
    float uu = uvx[(size_t)n * ld + j];
    float degf = (float)deg;
    float degc = fmaxf(degf, 1.f);
    float mean = (deg > 0) ? (uu + s / degf) : 0.f;
    float s2f = degf * uu * uu + 2.f * uu * s + s2;
    float var = fmaxf(s2f / degc - mean * mean, 0.f);
    float sd = sqrtf(var + 1e-5f);
    float mnv = (deg > 0) ? (uu + mn) : 0.f;
    float mxv = (deg > 0) ? (uu + mx) : 0.f;
    int t = j / F, f = j % F;
    size_t base = (size_t)n * (4 * C) + t * (4 * F);
    bsplit(mean, aggh + base + f, aggl + base + f);
    bsplit(mnv, aggh + base + F + f, aggl + base + F + f);
    bsplit(mxv, aggh + base + 2 * F + f, aggl + base + 2 * F + f);
    bsplit(sd, aggh + base + 3 * F + f, aggl + base + 3 * F + f);
    if (j == 0) {
        float dl = logf(degc + 1.f);
        alpha[n] = dl / avg_log[0];
        beta[n] = avg_log[0] / dl;
    }
}

// ---------------- combine (float4): post = px + p1 + a*p2 + b*p3 -> bf16 hi/lo ----------------
template <int C, int F>
__global__ void k_combine(const float* __restrict__ uvx, int ld, int pxoff,
                          const float* __restrict__ pc, int ldpc,
                          const float* __restrict__ alpha, const float* __restrict__ beta,
                          __nv_bfloat16* __restrict__ oh, __nv_bfloat16* __restrict__ ol) {
    int idx = blockIdx.x * blockDim.x + threadIdx.x;  // over NN*C/4
    if (idx < NN * C / 4) {
        int n = idx / (C / 4);
        int c4 = (idx % (C / 4)) * 4;
        int t = c4 / F, f = c4 % F;
        const float* p = pc + (size_t)n * ldpc + t * 3 * F;
        float al = alpha[n], be = beta[n];
        float4 p1 = *(const float4*)(p + f);
        float4 p2 = *(const float4*)(p + F + f);
        float4 p3 = *(const float4*)(p + 2 * F + f);
        float4 px = *(const float4*)(uvx + (size_t)n * ld + pxoff + c4);
        float o0 = px.x + p1.x + al * p2.x + be * p3.x;
        float o1 = px.y + p1.y + al * p2.y + be * p3.y;
        float o2 = px.z + p1.z + al * p2.z + be * p3.z;
        float o3 = px.w + p1.w + al * p2.w + be * p3.w;
        uint32_t l0, l1;
        uint32_t h0 = pack_hi2(o0, o1, &l0);
        uint32_t h1 = pack_hi2(o2, o3, &l1);
        size_t ob = (size_t)n * C + c4;
        *(uint2*)(oh + ob) = make_uint2(h0, h1);
        *(uint2*)(ol + ob) = make_uint2(l0, l1);
    }
}

// ---------------- batchnorm ----------------
__global__ void k_bnstats(const float* __restrict__ Y, float* __restrict__ sum,
                          float* __restrict__ sq, int M, int C) {
    int j = threadIdx.x;
    if (j >= C) return;
    float s = 0.f, q = 0.f;
    for (int r = blockIdx.x; r < M; r += gridDim.x) {
        float v = Y[(size_t)r * C + j];
        if (!isfinite(v)) v = 0.f;
        s += v;
        q += v * v;
    }
    atomicAdd(&sum[j], s);
    atomicAdd(&sq[j], q);
}
// relu(bn) -> bf16 hi/lo (float4)
__global__ void k_bnapply_split(const float* __restrict__ Y, const float* __restrict__ sum,
                                const float* __restrict__ sq, const float* __restrict__ g,
                                const float* __restrict__ b, __nv_bfloat16* __restrict__ oh,
                                __nv_bfloat16* __restrict__ ol, int M, int C) {
    int idx = blockIdx.x * blockDim.x + threadIdx.x;
    if (idx < M * C / 4) {
        int j = (idx * 4) % C;
        float4 y = ((const float4*)Y)[idx];
        float4 sm = *(const float4*)(sum + j);
        float4 qq = *(const float4*)(sq + j);
        float4 gg = *(const float4*)(g + j);
        float4 bb = *(const float4*)(b + j);
        float invM = 1.f / (float)M;
        float o[4];
        float ms[4] = {sm.x, sm.y, sm.z, sm.w};
        float qs[4] = {qq.x, qq.y, qq.z, qq.w};
        float gs[4] = {gg.x, gg.y, gg.z, gg.w};
        float bs[4] = {bb.x, bb.y, bb.z, bb.w};
        float ys[4] = {y.x, y.y, y.z, y.w};
#pragma unroll
        for (int q2 = 0; q2 < 4; q2++) {
            float m = ms[q2] * invM;
            float var = qs[q2] * invM - m * m;
            float inv = rsqrtf(var + 1e-5f);
            float yv = ys[q2];
            if (!isfinite(yv)) yv = 0.f;
            o[q2] = fmaxf(0.f, gs[q2] * (yv - m) * inv + bs[q2]);
        }
        uint32_t l0, l1;
        uint32_t h0 = pack_hi2(o[0], o[1], &l0);
        uint32_t h1 = pack_hi2(o[2], o[3], &l1);
        ((uint2*)oh)[idx] = make_uint2(h0, h1);
        ((uint2*)ol)[idx] = make_uint2(l0, l1);
    }
}
// relu(bn) -> fp32 (final output, float4)
__global__ void k_bnapply_out(const float* __restrict__ Y, const float* __restrict__ sum,
                              const float* __restrict__ sq, const float* __restrict__ g,
                              const float* __restrict__ b, float* __restrict__ OUT, int M,
                              int C) {
    int idx = blockIdx.x * blockDim.x + threadIdx.x;
    if (idx < M * C / 4) {
        int j = (idx * 4) % C;
        float4 y = ((const float4*)Y)[idx];
        float4 sm = *(const float4*)(sum + j);
        float4 qq = *(const float4*)(sq + j);
        float4 gg = *(const float4*)(g + j);
        float4 bb = *(const float4*)(b + j);
        float invM = 1.f / (float)M;
        float ms[4] = {sm.x, sm.y, sm.z, sm.w};
        float qs[4] = {qq.x, qq.y, qq.z, qq.w};
        float gs[4] = {gg.x, gg.y, gg.z, gg.w};
        float bs[4] = {bb.x, bb.y, bb.z, bb.w};
        float ys[4] = {y.x, y.y, y.z, y.w};
        float4 o;
        float* op = &o.x;
#pragma unroll
        for (int q2 = 0; q2 < 4; q2++) {
            float m = ms[q2] * invM;
            float var = qs[q2] * invM - m * m;
            float inv = rsqrtf(var + 1e-5f);
            float yv = ys[q2];
            if (!isfinite(yv)) yv = 0.f;
            op[q2] = fmaxf(0.f, gs[q2] * (yv - m) * inv + bs[q2]);
        }
        ((float4*)OUT)[idx] = o;
    }
}

// ---------------- launch ----------------
extern "C" void kernel_launch(void* const* d_in, const int* in_sizes, int n_in,
                              void* d_out, int out_size) {
    const float* x       = (const float*)d_in[0];
    const int*   eidx    = (const int*)d_in[1];
    const float* avg_log = (const float*)d_in[2];
    const float* pre1W   = (const float*)d_in[3];
    const float* pre1b   = (const float*)d_in[4];
    const float* post1W  = (const float*)d_in[5];
    const float* post1b  = (const float*)d_in[6];
    const float* lin1W   = (const float*)d_in[7];
    const float* lin1b   = (const float*)d_in[8];
    const float* bn1g    = (const float*)d_in[9];
    const float* bn1b    = (const float*)d_in[10];
    const float* pre2W   = (const float*)d_in[11];
    const float* pre2b   = (const float*)d_in[12];
    const float* post2W  = (const float*)d_in[13];
    const float* post2b  = (const float*)d_in[14];
    const float* lin2W   = (const float*)d_in[15];
    const float* lin2b   = (const float*)d_in[16];
    const float* bn2g    = (const float*)d_in[17];
    const float* bn2b    = (const float*)d_in[18];

    int* deg;
    float *uvx, *pc, *lin, *alpha, *beta, *bnsum, *bnsq, *bias;
    __nv_bfloat16 *xh, *xl, *hh, *hl, *aggh, *aggl, *posth, *postl, *ph, *pl;
    cudaGetSymbolAddress((void**)&deg, g_deg);
    cudaGetSymbolAddress((void**)&uvx, g_uvx);
    cudaGetSymbolAddress((void**)&pc, g_pc);
    cudaGetSymbolAddress((void**)&lin, g_lin);
    cudaGetSymbolAddress((void**)&alpha, g_alpha);
    cudaGetSymbolAddress((void**)&beta, g_beta);
    cudaGetSymbolAddress((void**)&bnsum, g_bnsum);
    cudaGetSymbolAddress((void**)&bnsq, g_bnsq);
    cudaGetSymbolAddress((void**)&bias, g_bias);
    cudaGetSymbolAddress((void**)&xh, g_xh);
    cudaGetSymbolAddress((void**)&xl, g_xl);
    cudaGetSymbolAddress((void**)&hh, g_hh);
    cudaGetSymbolAddress((void**)&hl, g_hl);
    cudaGetSymbolAddress((void**)&aggh, g_aggh);
    cudaGetSymbolAddress((void**)&aggl, g_aggl);
    cudaGetSymbolAddress((void**)&posth, g_posth);
    cudaGetSymbolAddress((void**)&postl, g_postl);
    cudaGetSymbolAddress((void**)&ph, g_ph);
    cudaGetSymbolAddress((void**)&pl, g_pl);

    const int SMEM = 61440;
    cudaFuncSetAttribute(k_gemm2, cudaFuncAttributeMaxDynamicSharedMemorySize, SMEM);

    const int mt = (NN + 127) / 128;  // 196

    // =================== layer 1 (Fin=128, F=64, TF=256) ===================
    k_prep<<<512, 256>>>(pre1W, pre1b, post1W, post1b, lin1W, lin1b, 128, 64, 256, 256);
    k_split<<<(NN * 32 + 255) / 256, 256>>>(x, xh, xl, NN * 32);
    k_zero_int<<<(NN + 255) / 256, 256>>>(deg, NN);
    k_hist<<<(EE + 255) / 256, 256>>>(eidx);
    k_scan<<<1, 1024>>>();
    // merged u|v|px : [NN,768] = x @ B_uvx
    k_gemm2<<<dim3(mt, 12, 1), 256, SMEM>>>(xh, xl, 128, 0, ph + OFF_UVX, pl + OFF_UVX,
                                            0, 768, bias, uvx, 768, 0, 0, NN, 128);
    k_scatter<<<(EE + 255) / 256, 256>>>(eidx);

    k_segreduce<256, 64><<<NN, 256>>>(uvx, 768, 256, aggh, aggl, alpha, beta, avg_log);
    k_gemm2<<<dim3(mt, 3, 4), 256, SMEM>>>(aggh, aggl, 1024, 256, ph + OFF_CAT, pl + OFF_CAT,
                                           192 * 256, 192, nullptr, pc, 768, 0, 192, NN, 256);
    k_combine<256, 64><<<(NN * 64 + 255) / 256, 256>>>(uvx, 768, 512, pc, 768, alpha, beta,
                                                       posth, postl);
    k_gemm2<<<dim3(mt, 4, 1), 256, SMEM>>>(posth, postl, 256, 0, ph + OFF_LIN, pl + OFF_LIN,
                                           0, 256, bias + 768, lin, 256, 0, 0, NN, 256);
    k_zero_f<<<1, 256>>>(bnsum, 256);
    k_zero_f<<<1, 256>>>(bnsq, 256);
    k_bnstats<<<512, 256>>>(lin, bnsum, bnsq, NN, 256);
    k_bnapply_split<<<(NN * 64 + 255) / 256, 256>>>(lin, bnsum, bnsq, bn1g, bn1b, hh, hl,
                                                    NN, 256);

    // =================== layer 2 (Fin=256, F=32, TF=128) ===================
    k_prep<<<512, 256>>>(pre2W, pre2b, post2W, post2b, lin2W, lin2b, 256, 32, 128, 128);
    k_gemm2<<<dim3(mt, 6, 1), 256, SMEM>>>(hh, hl, 256, 0, ph + OFF_UVX, pl + OFF_UVX,
                                           0, 384, bias, uvx, 384, 0, 0, NN, 256);
    k_segreduce<128, 32><<<NN, 128>>>(uvx, 384, 128, aggh, aggl, alpha, beta, avg_log);
    k_gemm2<<<dim3(mt, 2, 4), 256, SMEM>>>(aggh, aggl, 512, 128, ph + OFF_CAT, pl + OFF_CAT,
                                           96 * 128, 96, nullptr, pc, 384, 0, 96, NN, 128);
    k_combine<128, 32><<<(NN * 32 + 255) / 256, 256>>>(uvx, 384, 256, pc, 384, alpha, beta,
                                                       posth, postl);
    k_gemm2<<<dim3(mt, 2, 1), 256, SMEM>>>(posth, postl, 128, 0, ph + OFF_LIN, pl + OFF_LIN,
                                           0, 128, bias + 768, lin, 128, 0, 0, NN, 128);
    k_zero_f<<<1, 256>>>(bnsum, 256);
    k_zero_f<<<1, 256>>>(bnsq, 256);
    k_bnstats<<<512, 128>>>(lin, bnsum, bnsq, NN, 128);
    k_bnapply_out<<<(NN * 32 + 255) / 256, 256>>>(lin, bnsum, bnsq, bn2g, bn2b,
                                                  (float*)d_out, NN, 128);
}